// round 5
// baseline (speedup 1.0000x reference)
#include <cuda_runtime.h>
#include <cuda_bf16.h>
#include <math.h>
#include <float.h>

#define N_NODES 100000
#define IN_F    512
#define HID_F   128
#define OUT_F   40

// ---------------- scratch (device globals; no allocation allowed) ----------------
__device__ int   d_deg [N_NODES];
__device__ float d_dinv[N_NODES];
__device__ float d_g1  [(size_t)N_NODES * HID_F];
__device__ float d_acc1[(size_t)N_NODES * HID_F];
__device__ float d_a1  [(size_t)N_NODES * HID_F];
__device__ float d_g2  [(size_t)N_NODES * OUT_F];
__device__ float d_acc2[(size_t)N_NODES * OUT_F];

// ---------------- degree / norm ----------------
__global__ void zero_deg_kernel() {
    int i = blockIdx.x * blockDim.x + threadIdx.x;
    if (i < N_NODES) d_deg[i] = 0;
}

__global__ void count_deg_kernel(const int* __restrict__ dst, int E) {
    int i = blockIdx.x * blockDim.x + threadIdx.x;
    int stride = gridDim.x * blockDim.x;
    for (; i < E; i += stride) {
        atomicAdd(&d_deg[dst[i]], 1);
    }
}

__global__ void dinv_kernel() {
    int i = blockIdx.x * blockDim.x + threadIdx.x;
    if (i < N_NODES) {
        d_dinv[i] = rsqrtf((float)d_deg[i] + 1.0f);  // +1 self loop; always > 0
    }
}

// ---------------- GEMM1: g1 = (X @ W1) * dinv[row]; acc1 = 0 ----------------
// 128x128 block tile, BK=16, 256 threads, 8x8 per thread.
__global__ __launch_bounds__(256) void gemm1_kernel(const float* __restrict__ X,
                                                    const float* __restrict__ W) {
    __shared__ float As[16][128];   // As[k][m]
    __shared__ float Bs[16][128];   // Bs[k][n]
    const int tid = threadIdx.x;
    const int block_row = blockIdx.x * 128;
    const int tx = tid & 15;       // 0..15 -> col group
    const int ty = tid >> 4;       // 0..15 -> row group

    float acc[8][8];
#pragma unroll
    for (int i = 0; i < 8; i++)
#pragma unroll
        for (int j = 0; j < 8; j++) acc[i][j] = 0.0f;

    for (int k0 = 0; k0 < IN_F; k0 += 16) {
        // Load A tile: 128 rows x 16 cols = 512 float4, 2 per thread
#pragma unroll
        for (int i = 0; i < 2; i++) {
            int q  = tid + i * 256;
            int r  = q >> 2;
            int c4 = (q & 3) * 4;
            int grow = block_row + r;
            float4 v = make_float4(0.f, 0.f, 0.f, 0.f);
            if (grow < N_NODES)
                v = *(const float4*)(X + (size_t)grow * IN_F + k0 + c4);
            As[c4 + 0][r] = v.x; As[c4 + 1][r] = v.y;
            As[c4 + 2][r] = v.z; As[c4 + 3][r] = v.w;
        }
        // Load B tile: 16 rows x 128 cols = 512 float4, 2 per thread
#pragma unroll
        for (int i = 0; i < 2; i++) {
            int q  = tid + i * 256;
            int kr = q >> 5;
            int c4 = (q & 31) * 4;
            *(float4*)(&Bs[kr][c4]) = *(const float4*)(W + (size_t)(k0 + kr) * HID_F + c4);
        }
        __syncthreads();
#pragma unroll
        for (int k = 0; k < 16; k++) {
            float a[8], b[8];
            *(float4*)(a)     = *(float4*)(&As[k][ty * 8]);
            *(float4*)(a + 4) = *(float4*)(&As[k][ty * 8 + 4]);
            *(float4*)(b)     = *(float4*)(&Bs[k][tx * 8]);
            *(float4*)(b + 4) = *(float4*)(&Bs[k][tx * 8 + 4]);
#pragma unroll
            for (int i = 0; i < 8; i++)
#pragma unroll
                for (int j = 0; j < 8; j++) acc[i][j] = fmaf(a[i], b[j], acc[i][j]);
        }
        __syncthreads();
    }

    const float4 z4 = make_float4(0.f, 0.f, 0.f, 0.f);
#pragma unroll
    for (int i = 0; i < 8; i++) {
        int grow = block_row + ty * 8 + i;
        if (grow >= N_NODES) break;
        float dv = d_dinv[grow];
#pragma unroll
        for (int j4 = 0; j4 < 8; j4 += 4) {
            int col = tx * 8 + j4;
            float4 v = make_float4(acc[i][j4] * dv, acc[i][j4 + 1] * dv,
                                   acc[i][j4 + 2] * dv, acc[i][j4 + 3] * dv);
            *(float4*)(d_g1   + (size_t)grow * HID_F + col) = v;
            *(float4*)(d_acc1 + (size_t)grow * HID_F + col) = z4;
        }
    }
}

// ---------------- scatter1: acc1[dst] += g1[src] (one warp per edge) ----------------
__global__ __launch_bounds__(256) void scatter1_kernel(const int* __restrict__ src,
                                                       const int* __restrict__ dst, int E) {
    int warp = (blockIdx.x * blockDim.x + threadIdx.x) >> 5;
    int lane = threadIdx.x & 31;
    if (warp >= E) return;
    int s = src[warp];
    int d = dst[warp];
    float4 v = *((const float4*)(d_g1 + (size_t)s * HID_F) + lane);
    float* pd = d_acc1 + (size_t)d * HID_F + lane * 4;
    atomicAdd(pd + 0, v.x);
    atomicAdd(pd + 1, v.y);
    atomicAdd(pd + 2, v.z);
    atomicAdd(pd + 3, v.w);
}

// ---------------- finalize1: a1 = relu(dinv*(acc1+g1) + b1) ----------------
__global__ __launch_bounds__(256) void finalize1_kernel(const float* __restrict__ b1) {
    const int total4 = N_NODES * (HID_F / 4);
    int i = blockIdx.x * blockDim.x + threadIdx.x;
    int stride = gridDim.x * blockDim.x;
    for (; i < total4; i += stride) {
        int row  = i >> 5;          // /32 float4 per row
        int col4 = (i & 31) * 4;
        float dv = d_dinv[row];
        float4 a = *((const float4*)d_acc1 + i);
        float4 g = *((const float4*)d_g1 + i);
        float4 b = *(const float4*)(b1 + col4);
        float4 o;
        o.x = fmaxf(dv * (a.x + g.x) + b.x, 0.f);
        o.y = fmaxf(dv * (a.y + g.y) + b.y, 0.f);
        o.z = fmaxf(dv * (a.z + g.z) + b.z, 0.f);
        o.w = fmaxf(dv * (a.w + g.w) + b.w, 0.f);
        *((float4*)d_a1 + i) = o;
    }
}

// ---------------- GEMM2: g2 = (a1 @ W2) * dinv; acc2 = 0 ----------------
// 32 rows per block, 256 threads as 32x8; thread = (row ty, 5 cols at tx*5).
__global__ __launch_bounds__(256) void gemm2_kernel(const float* __restrict__ W2) {
    __shared__ float As[32][132];     // padded to kill bank conflicts
    __shared__ float Ws[128][40];
    const int tid = threadIdx.x;
    const int block_row = blockIdx.x * 32;
    const int tx = tid & 7;
    const int ty = tid >> 3;

    // load A tile: 32 rows x 128 = 1024 float4, 4 per thread
#pragma unroll
    for (int i = 0; i < 4; i++) {
        int q  = tid + i * 256;
        int r  = q >> 5;
        int c4 = (q & 31) * 4;
        int grow = block_row + r;
        float4 v = make_float4(0.f, 0.f, 0.f, 0.f);
        if (grow < N_NODES)
            v = *(const float4*)(d_a1 + (size_t)grow * HID_F + c4);
        *(float4*)(&As[r][c4]) = v;
    }
    // load W2: 128x40 = 1280 float4, 5 per thread
#pragma unroll
    for (int i = 0; i < 5; i++) {
        int q  = tid + i * 256;
        int kr = q / 10;
        int c4 = (q % 10) * 4;
        *(float4*)(&Ws[kr][c4]) = *(const float4*)(W2 + (size_t)kr * OUT_F + c4);
    }
    __syncthreads();

    float acc[5] = {0.f, 0.f, 0.f, 0.f, 0.f};
#pragma unroll 8
    for (int k = 0; k < 128; k++) {
        float a = As[ty][k];
#pragma unroll
        for (int j = 0; j < 5; j++) acc[j] = fmaf(a, Ws[k][tx * 5 + j], acc[j]);
    }

    int grow = block_row + ty;
    if (grow < N_NODES) {
        float dv = d_dinv[grow];
#pragma unroll
        for (int j = 0; j < 5; j++) {
            d_g2  [(size_t)grow * OUT_F + tx * 5 + j] = acc[j] * dv;
            d_acc2[(size_t)grow * OUT_F + tx * 5 + j] = 0.f;
        }
    }
}

// ---------------- scatter2: acc2[dst] += g2[src] (lanes 0..9 carry float4) ----------------
__global__ __launch_bounds__(256) void scatter2_kernel(const int* __restrict__ src,
                                                       const int* __restrict__ dst, int E) {
    int warp = (blockIdx.x * blockDim.x + threadIdx.x) >> 5;
    int lane = threadIdx.x & 31;
    if (warp >= E) return;
    int s = src[warp];
    int d = dst[warp];
    if (lane < OUT_F / 4) {
        float4 v = *((const float4*)(d_g2 + (size_t)s * OUT_F) + lane);
        float* pd = d_acc2 + (size_t)d * OUT_F + lane * 4;
        atomicAdd(pd + 0, v.x);
        atomicAdd(pd + 1, v.y);
        atomicAdd(pd + 2, v.z);
        atomicAdd(pd + 3, v.w);
    }
}

// ---------------- final: o = dinv*(acc2+g2)+b2, then log_softmax per row ----------------
__global__ __launch_bounds__(256) void final_kernel(const float* __restrict__ b2,
                                                    float* __restrict__ out) {
    int warp = (blockIdx.x * blockDim.x + threadIdx.x) >> 5;
    int lane = threadIdx.x & 31;
    if (warp >= N_NODES) return;
    float dv = d_dinv[warp];
    const float* ar = d_acc2 + (size_t)warp * OUT_F;
    const float* gr = d_g2   + (size_t)warp * OUT_F;

    float v0 = -FLT_MAX, v1 = -FLT_MAX;
    if (lane < OUT_F)      v0 = dv * (ar[lane]      + gr[lane])      + b2[lane];
    if (lane + 32 < OUT_F) v1 = dv * (ar[lane + 32] + gr[lane + 32]) + b2[lane + 32];

    float m = fmaxf(v0, v1);
#pragma unroll
    for (int o = 16; o > 0; o >>= 1) m = fmaxf(m, __shfl_xor_sync(0xFFFFFFFFu, m, o));

    float e = 0.f;
    if (lane < OUT_F)      e += __expf(v0 - m);
    if (lane + 32 < OUT_F) e += __expf(v1 - m);
#pragma unroll
    for (int o = 16; o > 0; o >>= 1) e += __shfl_xor_sync(0xFFFFFFFFu, e, o);

    float ls = m + __logf(e);
    if (lane < OUT_F)      out[(size_t)warp * OUT_F + lane]      = v0 - ls;
    if (lane + 32 < OUT_F) out[(size_t)warp * OUT_F + lane + 32] = v1 - ls;
}

// ---------------- launch ----------------
extern "C" void kernel_launch(void* const* d_in, const int* in_sizes, int n_in,
                              void* d_out, int out_size) {
    const float* x   = (const float*)d_in[0];
    const int*   ei  = (const int*)d_in[1];     // JAX demotes int64 -> int32
    const float* W1  = (const float*)d_in[2];
    const float* b1  = (const float*)d_in[3];
    const float* W2  = (const float*)d_in[4];
    const float* b2  = (const float*)d_in[5];
    float*       out = (float*)d_out;

    const int E = in_sizes[1] / 2;
    const int* src = ei;
    const int* dst = ei + E;

    // degrees + dinv
    zero_deg_kernel<<<(N_NODES + 255) / 256, 256>>>();
    count_deg_kernel<<<4096, 256>>>(dst, E);
    dinv_kernel<<<(N_NODES + 255) / 256, 256>>>();

    // layer 1
    gemm1_kernel<<<(N_NODES + 127) / 128, 256>>>(x, W1);
    {
        long long threads = (long long)E * 32;
        scatter1_kernel<<<(int)((threads + 255) / 256), 256>>>(src, dst, E);
    }
    finalize1_kernel<<<12500, 256>>>(b1);

    // layer 2
    gemm2_kernel<<<(N_NODES + 31) / 32, 256>>>(W2);
    {
        long long threads = (long long)E * 32;
        scatter2_kernel<<<(int)((threads + 255) / 256), 256>>>(src, dst, E);
    }
    final_kernel<<<(N_NODES * 32 + 255) / 256, 256>>>(b2, out);
}

// round 7
// speedup vs baseline: 1.5063x; 1.5063x over previous
#include <cuda_runtime.h>
#include <cuda_bf16.h>
#include <math.h>
#include <float.h>

#define N_NODES 100000
#define E_MAX   1600000
#define IN_F    512
#define HID_F   128
#define OUT_F   40

// ---------------- scratch (device globals; no allocation allowed) ----------------
__device__ int   d_deg    [N_NODES];
__device__ int   d_rowptr [N_NODES + 1];
__device__ int   d_cursor [N_NODES];
__device__ int   d_csr_src[E_MAX];
__device__ float d_dinv[N_NODES];
__device__ float d_g1  [(size_t)N_NODES * HID_F];
__device__ float d_a1  [(size_t)N_NODES * HID_F];
__device__ float d_g2  [(size_t)N_NODES * OUT_F];

// ---------------- degree / norm ----------------
__global__ void zero_deg_kernel() {
    int i = blockIdx.x * blockDim.x + threadIdx.x;
    if (i < N_NODES) d_deg[i] = 0;
}

__global__ void count_deg_kernel(const int* __restrict__ dst, int E) {
    int i = blockIdx.x * blockDim.x + threadIdx.x;
    int stride = gridDim.x * blockDim.x;
    for (; i < E; i += stride) {
        atomicAdd(&d_deg[dst[i]], 1);
    }
}

__global__ void dinv_kernel() {
    int i = blockIdx.x * blockDim.x + threadIdx.x;
    if (i < N_NODES) {
        d_dinv[i] = rsqrtf((float)d_deg[i] + 1.0f);  // +1 self loop; always > 0
    }
}

// ---------------- scan: rowptr = exclusive_scan(deg); cursor = 0 ----------------
__global__ __launch_bounds__(1024) void scan_kernel() {
    __shared__ int partial[1024];
    const int T = 1024;
    int tid = threadIdx.x;
    const int chunk = (N_NODES + T - 1) / T;   // 98
    int begin = tid * chunk;
    int endi  = min(begin + chunk, N_NODES);

    int s = 0;
    for (int i = begin; i < endi; i++) s += d_deg[i];
    partial[tid] = s;
    __syncthreads();
    // Hillis-Steele inclusive scan
    for (int off = 1; off < T; off <<= 1) {
        int v = (tid >= off) ? partial[tid - off] : 0;
        __syncthreads();
        partial[tid] += v;
        __syncthreads();
    }
    int run = (tid > 0) ? partial[tid - 1] : 0;
    for (int i = begin; i < endi; i++) {
        d_rowptr[i] = run;
        d_cursor[i] = 0;
        run += d_deg[i];
    }
    if (endi == N_NODES && begin < N_NODES) d_rowptr[N_NODES] = run;
}

// ---------------- fill: bucket edges by dst ----------------
__global__ void fill_kernel(const int* __restrict__ src, const int* __restrict__ dst, int E) {
    int i = blockIdx.x * blockDim.x + threadIdx.x;
    int stride = gridDim.x * blockDim.x;
    for (; i < E; i += stride) {
        int d = dst[i];
        int pos = d_rowptr[d] + atomicAdd(&d_cursor[d], 1);
        d_csr_src[pos] = src[i];
    }
}

// ---------------- GEMM1: g1 = (X @ W1) * dinv[row] ----------------
// 128x128 block tile, BK=16, 256 threads, 8x8 per thread.
__global__ __launch_bounds__(256) void gemm1_kernel(const float* __restrict__ X,
                                                    const float* __restrict__ W) {
    __shared__ float As[16][128];   // As[k][m]
    __shared__ float Bs[16][128];   // Bs[k][n]
    const int tid = threadIdx.x;
    const int block_row = blockIdx.x * 128;
    const int tx = tid & 15;
    const int ty = tid >> 4;

    float acc[8][8];
#pragma unroll
    for (int i = 0; i < 8; i++)
#pragma unroll
        for (int j = 0; j < 8; j++) acc[i][j] = 0.0f;

    for (int k0 = 0; k0 < IN_F; k0 += 16) {
#pragma unroll
        for (int i = 0; i < 2; i++) {
            int q  = tid + i * 256;
            int r  = q >> 2;
            int c4 = (q & 3) * 4;
            int grow = block_row + r;
            float4 v = make_float4(0.f, 0.f, 0.f, 0.f);
            if (grow < N_NODES)
                v = *(const float4*)(X + (size_t)grow * IN_F + k0 + c4);
            As[c4 + 0][r] = v.x; As[c4 + 1][r] = v.y;
            As[c4 + 2][r] = v.z; As[c4 + 3][r] = v.w;
        }
#pragma unroll
        for (int i = 0; i < 2; i++) {
            int q  = tid + i * 256;
            int kr = q >> 5;
            int c4 = (q & 31) * 4;
            *(float4*)(&Bs[kr][c4]) = *(const float4*)(W + (size_t)(k0 + kr) * HID_F + c4);
        }
        __syncthreads();
#pragma unroll
        for (int k = 0; k < 16; k++) {
            float a[8], b[8];
            *(float4*)(a)     = *(float4*)(&As[k][ty * 8]);
            *(float4*)(a + 4) = *(float4*)(&As[k][ty * 8 + 4]);
            *(float4*)(b)     = *(float4*)(&Bs[k][tx * 8]);
            *(float4*)(b + 4) = *(float4*)(&Bs[k][tx * 8 + 4]);
#pragma unroll
            for (int i = 0; i < 8; i++)
#pragma unroll
                for (int j = 0; j < 8; j++) acc[i][j] = fmaf(a[i], b[j], acc[i][j]);
        }
        __syncthreads();
    }

#pragma unroll
    for (int i = 0; i < 8; i++) {
        int grow = block_row + ty * 8 + i;
        if (grow >= N_NODES) break;
        float dv = d_dinv[grow];
#pragma unroll
        for (int j4 = 0; j4 < 8; j4 += 4) {
            int col = tx * 8 + j4;
            float4 v = make_float4(acc[i][j4] * dv, acc[i][j4 + 1] * dv,
                                   acc[i][j4 + 2] * dv, acc[i][j4 + 3] * dv);
            *(float4*)(d_g1 + (size_t)grow * HID_F + col) = v;
        }
    }
}

// ---------------- gather1: a1 = relu(dinv*(sum_in g1[src] + g1[n]) + b1) ----------------
// One warp per node; lane owns one float4 (4 of 128 cols). 2-way edge unroll.
__global__ __launch_bounds__(256) void gather1_kernel(const float* __restrict__ b1) {
    int n    = (blockIdx.x * blockDim.x + threadIdx.x) >> 5;
    int lane = threadIdx.x & 31;
    if (n >= N_NODES) return;
    int e   = d_rowptr[n];
    int end = d_rowptr[n + 1];

    const float4* G = (const float4*)d_g1;
    float4 a0 = make_float4(0.f, 0.f, 0.f, 0.f);
    float4 a1v = make_float4(0.f, 0.f, 0.f, 0.f);

    for (; e + 1 < end; e += 2) {
        int s0 = d_csr_src[e];
        int s1 = d_csr_src[e + 1];
        float4 v0 = G[(size_t)s0 * 32 + lane];
        float4 v1 = G[(size_t)s1 * 32 + lane];
        a0.x += v0.x; a0.y += v0.y; a0.z += v0.z; a0.w += v0.w;
        a1v.x += v1.x; a1v.y += v1.y; a1v.z += v1.z; a1v.w += v1.w;
    }
    if (e < end) {
        int s0 = d_csr_src[e];
        float4 v0 = G[(size_t)s0 * 32 + lane];
        a0.x += v0.x; a0.y += v0.y; a0.z += v0.z; a0.w += v0.w;
    }
    float4 self = G[(size_t)n * 32 + lane];
    float dv = d_dinv[n];
    float4 b = *(const float4*)(b1 + lane * 4);
    float4 o;
    o.x = fmaxf(dv * (a0.x + a1v.x + self.x) + b.x, 0.f);
    o.y = fmaxf(dv * (a0.y + a1v.y + self.y) + b.y, 0.f);
    o.z = fmaxf(dv * (a0.z + a1v.z + self.z) + b.z, 0.f);
    o.w = fmaxf(dv * (a0.w + a1v.w + self.w) + b.w, 0.f);
    *((float4*)d_a1 + (size_t)n * 32 + lane) = o;
}

// ---------------- GEMM2: g2 = (a1 @ W2) * dinv ----------------
__global__ __launch_bounds__(256) void gemm2_kernel(const float* __restrict__ W2) {
    __shared__ float As[32][132];
    __shared__ float Ws[128][40];
    const int tid = threadIdx.x;
    const int block_row = blockIdx.x * 32;
    const int tx = tid & 7;
    const int ty = tid >> 3;

#pragma unroll
    for (int i = 0; i < 4; i++) {
        int q  = tid + i * 256;
        int r  = q >> 5;
        int c4 = (q & 31) * 4;
        int grow = block_row + r;
        float4 v = make_float4(0.f, 0.f, 0.f, 0.f);
        if (grow < N_NODES)
            v = *(const float4*)(d_a1 + (size_t)grow * HID_F + c4);
        *(float4*)(&As[r][c4]) = v;
    }
#pragma unroll
    for (int i = 0; i < 5; i++) {
        int q  = tid + i * 256;
        int kr = q / 10;
        int c4 = (q % 10) * 4;
        *(float4*)(&Ws[kr][c4]) = *(const float4*)(W2 + (size_t)kr * OUT_F + c4);
    }
    __syncthreads();

    float acc[5] = {0.f, 0.f, 0.f, 0.f, 0.f};
#pragma unroll 8
    for (int k = 0; k < 128; k++) {
        float a = As[ty][k];
#pragma unroll
        for (int j = 0; j < 5; j++) acc[j] = fmaf(a, Ws[k][tx * 5 + j], acc[j]);
    }

    int grow = block_row + ty;
    if (grow < N_NODES) {
        float dv = d_dinv[grow];
#pragma unroll
        for (int j = 0; j < 5; j++)
            d_g2[(size_t)grow * OUT_F + tx * 5 + j] = acc[j] * dv;
    }
}

// ---------------- gather2 + log_softmax fused ----------------
// One warp per node. Lanes 0..29: sub-edge = lane/10 (3 edges/iter), comp = lane%10 (float4).
__global__ __launch_bounds__(256) void gather2_kernel(const float* __restrict__ b2,
                                                      float* __restrict__ out) {
    int n    = (blockIdx.x * blockDim.x + threadIdx.x) >> 5;
    int lane = threadIdx.x & 31;
    if (n >= N_NODES) return;
    int start = d_rowptr[n];
    int end   = d_rowptr[n + 1];
    int deg   = end - start;

    const float4* G = (const float4*)d_g2;
    int sub  = lane / 10;       // 0..2 (lane 30,31 -> 3: inactive)
    int comp = lane % 10;
    bool active = lane < 30;

    float4 a = make_float4(0.f, 0.f, 0.f, 0.f);
    for (int base = 0; base < deg; base += 3) {
        int idx = base + sub;
        if (active && idx < deg) {
            int s = d_csr_src[start + idx];
            float4 v = G[(size_t)s * 10 + comp];
            a.x += v.x; a.y += v.y; a.z += v.z; a.w += v.w;
        }
    }
    // combine 3 sub-accumulators down to lanes 0..9
#pragma unroll
    for (int off = 10; off <= 20; off += 10) {
        float vx = __shfl_sync(0xFFFFFFFFu, a.x, lane + off < 32 ? lane + off : lane);
        float vy = __shfl_sync(0xFFFFFFFFu, a.y, lane + off < 32 ? lane + off : lane);
        float vz = __shfl_sync(0xFFFFFFFFu, a.z, lane + off < 32 ? lane + off : lane);
        float vw = __shfl_sync(0xFFFFFFFFu, a.w, lane + off < 32 ? lane + off : lane);
        if (lane < 10 && lane + off < 30) { a.x += vx; a.y += vy; a.z += vz; a.w += vw; }
    }

    float dv = d_dinv[n];
    float4 vals = make_float4(-FLT_MAX, -FLT_MAX, -FLT_MAX, -FLT_MAX);
    if (lane < 10) {
        float4 self = G[(size_t)n * 10 + lane];
        float4 b = *(const float4*)(b2 + lane * 4);
        vals.x = dv * (a.x + self.x) + b.x;
        vals.y = dv * (a.y + self.y) + b.y;
        vals.z = dv * (a.z + self.z) + b.z;
        vals.w = dv * (a.w + self.w) + b.w;
    }
    // warp max
    float m = fmaxf(fmaxf(vals.x, vals.y), fmaxf(vals.z, vals.w));
#pragma unroll
    for (int o = 16; o > 0; o >>= 1) m = fmaxf(m, __shfl_xor_sync(0xFFFFFFFFu, m, o));
    // warp sum of exp
    float esum = 0.f;
    if (lane < 10) {
        esum = __expf(vals.x - m) + __expf(vals.y - m) +
               __expf(vals.z - m) + __expf(vals.w - m);
    }
#pragma unroll
    for (int o = 16; o > 0; o >>= 1) esum += __shfl_xor_sync(0xFFFFFFFFu, esum, o);

    float ls = m + __logf(esum);
    if (lane < 10) {
        float4 o4 = make_float4(vals.x - ls, vals.y - ls, vals.z - ls, vals.w - ls);
        *((float4*)(out + (size_t)n * OUT_F) + lane) = o4;
    }
}

// ---------------- launch ----------------
extern "C" void kernel_launch(void* const* d_in, const int* in_sizes, int n_in,
                              void* d_out, int out_size) {
    const float* x   = (const float*)d_in[0];
    const int*   ei  = (const int*)d_in[1];     // JAX demotes int64 -> int32
    const float* W1  = (const float*)d_in[2];
    const float* b1  = (const float*)d_in[3];
    const float* W2  = (const float*)d_in[4];
    const float* b2  = (const float*)d_in[5];
    float*       out = (float*)d_out;

    const int E = in_sizes[1] / 2;
    const int* src = ei;
    const int* dst = ei + E;

    // CSR build
    zero_deg_kernel<<<(N_NODES + 255) / 256, 256>>>();
    count_deg_kernel<<<2048, 256>>>(dst, E);
    dinv_kernel<<<(N_NODES + 255) / 256, 256>>>();
    scan_kernel<<<1, 1024>>>();
    fill_kernel<<<2048, 256>>>(src, dst, E);

    // layer 1
    gemm1_kernel<<<(N_NODES + 127) / 128, 256>>>(x, W1);
    gather1_kernel<<<(N_NODES * 32 + 255) / 256, 256>>>(b1);

    // layer 2
    gemm2_kernel<<<(N_NODES + 31) / 32, 256>>>(W2);
    gather2_kernel<<<(N_NODES * 32 + 255) / 256, 256>>>(b2, out);
}

// round 8
// speedup vs baseline: 1.9244x; 1.2775x over previous
#include <cuda_runtime.h>
#include <cuda_bf16.h>
#include <math.h>
#include <float.h>

#define N_NODES 100000
#define E_MAX   1600000
#define IN_F    512
#define HID_F   128
#define OUT_F   40

#define SCAN_B  1024
#define N_SCAN_BLOCKS ((N_NODES + SCAN_B - 1) / SCAN_B)   // 98

// ---------------- scratch (device globals; no allocation allowed) ----------------
__device__ int   d_deg    [N_NODES];
__device__ int   d_rowptr [N_NODES + 1];
__device__ int   d_cursor [N_NODES];
__device__ int   d_csr_src[E_MAX];
__device__ int   d_blocksum[N_SCAN_BLOCKS];
__device__ int   d_blockoff[N_SCAN_BLOCKS + 1];
__device__ float d_dinv[N_NODES];
__device__ float d_g1  [(size_t)N_NODES * HID_F];
__device__ float d_a1  [(size_t)N_NODES * HID_F];
__device__ float d_g2  [(size_t)N_NODES * OUT_F];

// ---------------- degree / norm ----------------
__global__ void zero_deg_kernel() {
    int i = blockIdx.x * blockDim.x + threadIdx.x;
    if (i < N_NODES) d_deg[i] = 0;
}

__global__ void count_deg_kernel(const int* __restrict__ dst, int E) {
    int i = blockIdx.x * blockDim.x + threadIdx.x;
    int stride = gridDim.x * blockDim.x;
    for (; i < E; i += stride) {
        atomicAdd(&d_deg[dst[i]], 1);
    }
}

__global__ void dinv_kernel() {
    int i = blockIdx.x * blockDim.x + threadIdx.x;
    if (i < N_NODES) {
        d_dinv[i] = rsqrtf((float)d_deg[i] + 1.0f);  // +1 self loop; always > 0
    }
}

// ---------------- hierarchical scan ----------------
// Stage 1: per-block sums
__global__ __launch_bounds__(SCAN_B) void blocksum_kernel() {
    __shared__ int sh[SCAN_B / 32];
    int i = blockIdx.x * SCAN_B + threadIdx.x;
    int v = (i < N_NODES) ? d_deg[i] : 0;
#pragma unroll
    for (int o = 16; o > 0; o >>= 1) v += __shfl_xor_sync(0xFFFFFFFFu, v, o);
    if ((threadIdx.x & 31) == 0) sh[threadIdx.x >> 5] = v;
    __syncthreads();
    if (threadIdx.x < SCAN_B / 32) {
        int s = sh[threadIdx.x];
#pragma unroll
        for (int o = 16; o > 0; o >>= 1) s += __shfl_xor_sync(0xFFFFFFFFu, s, o);
        if (threadIdx.x == 0) d_blocksum[blockIdx.x] = s;
    }
}

// Stage 2: exclusive scan of the 98 block sums (1 warp handles it serial-free)
__global__ __launch_bounds__(128) void scan_tops_kernel() {
    __shared__ int sh[N_SCAN_BLOCKS];
    int tid = threadIdx.x;
    if (tid < N_SCAN_BLOCKS) sh[tid] = d_blocksum[tid];
    __syncthreads();
    if (tid == 0) {
        int run = 0;
        for (int i = 0; i < N_SCAN_BLOCKS; i++) { int t = sh[i]; sh[i] = run; run += t; }
        d_blockoff[N_SCAN_BLOCKS] = run;   // total E
    }
    __syncthreads();
    if (tid < N_SCAN_BLOCKS) d_blockoff[tid] = sh[tid];
}

// Stage 3: per-block exclusive scan + offset, write rowptr & cursor
__global__ __launch_bounds__(SCAN_B) void rowptr_kernel() {
    __shared__ int sh[SCAN_B];
    int tid = threadIdx.x;
    int i = blockIdx.x * SCAN_B + tid;
    int v = (i < N_NODES) ? d_deg[i] : 0;
    sh[tid] = v;
    __syncthreads();
    // Hillis-Steele inclusive scan over 1024
    for (int off = 1; off < SCAN_B; off <<= 1) {
        int t = (tid >= off) ? sh[tid - off] : 0;
        __syncthreads();
        sh[tid] += t;
        __syncthreads();
    }
    if (i < N_NODES) {
        int excl = sh[tid] - v;                 // exclusive
        d_rowptr[i] = d_blockoff[blockIdx.x] + excl;
        d_cursor[i] = 0;
    }
    if (i == N_NODES - 1 || (i < N_NODES && tid == SCAN_B - 1 && blockIdx.x == N_SCAN_BLOCKS - 1)) {
        // last node writes the sentinel
    }
    if (i == N_NODES - 1) d_rowptr[N_NODES] = d_blockoff[N_SCAN_BLOCKS];
}

// ---------------- fill: bucket edges by dst ----------------
__global__ void fill_kernel(const int* __restrict__ src, const int* __restrict__ dst, int E) {
    int i = blockIdx.x * blockDim.x + threadIdx.x;
    int stride = gridDim.x * blockDim.x;
    for (; i < E; i += stride) {
        int d = dst[i];
        int pos = d_rowptr[d] + atomicAdd(&d_cursor[d], 1);
        d_csr_src[pos] = src[i];
    }
}

// ---------------- GEMM1: g1 = (X @ W1) * dinv[row] ----------------
// 128x128 block tile, BK=16, 256 threads, 8x8 per thread.
__global__ __launch_bounds__(256) void gemm1_kernel(const float* __restrict__ X,
                                                    const float* __restrict__ W) {
    __shared__ float As[16][128];   // As[k][m]
    __shared__ float Bs[16][128];   // Bs[k][n]
    const int tid = threadIdx.x;
    const int block_row = blockIdx.x * 128;
    const int tx = tid & 15;
    const int ty = tid >> 4;

    float acc[8][8];
#pragma unroll
    for (int i = 0; i < 8; i++)
#pragma unroll
        for (int j = 0; j < 8; j++) acc[i][j] = 0.0f;

    for (int k0 = 0; k0 < IN_F; k0 += 16) {
#pragma unroll
        for (int i = 0; i < 2; i++) {
            int q  = tid + i * 256;
            int r  = q >> 2;
            int c4 = (q & 3) * 4;
            int grow = block_row + r;
            float4 v = make_float4(0.f, 0.f, 0.f, 0.f);
            if (grow < N_NODES)
                v = *(const float4*)(X + (size_t)grow * IN_F + k0 + c4);
            As[c4 + 0][r] = v.x; As[c4 + 1][r] = v.y;
            As[c4 + 2][r] = v.z; As[c4 + 3][r] = v.w;
        }
#pragma unroll
        for (int i = 0; i < 2; i++) {
            int q  = tid + i * 256;
            int kr = q >> 5;
            int c4 = (q & 31) * 4;
            *(float4*)(&Bs[kr][c4]) = *(const float4*)(W + (size_t)(k0 + kr) * HID_F + c4);
        }
        __syncthreads();
#pragma unroll
        for (int k = 0; k < 16; k++) {
            float a[8], b[8];
            *(float4*)(a)     = *(float4*)(&As[k][ty * 8]);
            *(float4*)(a + 4) = *(float4*)(&As[k][ty * 8 + 4]);
            *(float4*)(b)     = *(float4*)(&Bs[k][tx * 8]);
            *(float4*)(b + 4) = *(float4*)(&Bs[k][tx * 8 + 4]);
#pragma unroll
            for (int i = 0; i < 8; i++)
#pragma unroll
                for (int j = 0; j < 8; j++) acc[i][j] = fmaf(a[i], b[j], acc[i][j]);
        }
        __syncthreads();
    }

#pragma unroll
    for (int i = 0; i < 8; i++) {
        int grow = block_row + ty * 8 + i;
        if (grow >= N_NODES) break;
        float dv = d_dinv[grow];
#pragma unroll
        for (int j4 = 0; j4 < 8; j4 += 4) {
            int col = tx * 8 + j4;
            float4 v = make_float4(acc[i][j4] * dv, acc[i][j4 + 1] * dv,
                                   acc[i][j4 + 2] * dv, acc[i][j4 + 3] * dv);
            *(float4*)(d_g1 + (size_t)grow * HID_F + col) = v;
        }
    }
}

// ---------------- gather1: a1 = relu(dinv*(sum_in g1[src] + g1[n]) + b1) ----------------
__global__ __launch_bounds__(256) void gather1_kernel(const float* __restrict__ b1) {
    int n    = (blockIdx.x * blockDim.x + threadIdx.x) >> 5;
    int lane = threadIdx.x & 31;
    if (n >= N_NODES) return;
    int e   = d_rowptr[n];
    int end = d_rowptr[n + 1];

    const float4* G = (const float4*)d_g1;
    float4 a0 = make_float4(0.f, 0.f, 0.f, 0.f);
    float4 a1v = make_float4(0.f, 0.f, 0.f, 0.f);

    for (; e + 1 < end; e += 2) {
        int s0 = d_csr_src[e];
        int s1 = d_csr_src[e + 1];
        float4 v0 = G[(size_t)s0 * 32 + lane];
        float4 v1 = G[(size_t)s1 * 32 + lane];
        a0.x += v0.x; a0.y += v0.y; a0.z += v0.z; a0.w += v0.w;
        a1v.x += v1.x; a1v.y += v1.y; a1v.z += v1.z; a1v.w += v1.w;
    }
    if (e < end) {
        int s0 = d_csr_src[e];
        float4 v0 = G[(size_t)s0 * 32 + lane];
        a0.x += v0.x; a0.y += v0.y; a0.z += v0.z; a0.w += v0.w;
    }
    float4 self = G[(size_t)n * 32 + lane];
    float dv = d_dinv[n];
    float4 b = *(const float4*)(b1 + lane * 4);
    float4 o;
    o.x = fmaxf(dv * (a0.x + a1v.x + self.x) + b.x, 0.f);
    o.y = fmaxf(dv * (a0.y + a1v.y + self.y) + b.y, 0.f);
    o.z = fmaxf(dv * (a0.z + a1v.z + self.z) + b.z, 0.f);
    o.w = fmaxf(dv * (a0.w + a1v.w + self.w) + b.w, 0.f);
    *((float4*)d_a1 + (size_t)n * 32 + lane) = o;
}

// ---------------- GEMM2: g2 = (a1 @ W2) * dinv ----------------
__global__ __launch_bounds__(256) void gemm2_kernel(const float* __restrict__ W2) {
    __shared__ float As[32][132];
    __shared__ float Ws[128][40];
    const int tid = threadIdx.x;
    const int block_row = blockIdx.x * 32;
    const int tx = tid & 7;
    const int ty = tid >> 3;

#pragma unroll
    for (int i = 0; i < 4; i++) {
        int q  = tid + i * 256;
        int r  = q >> 5;
        int c4 = (q & 31) * 4;
        int grow = block_row + r;
        float4 v = make_float4(0.f, 0.f, 0.f, 0.f);
        if (grow < N_NODES)
            v = *(const float4*)(d_a1 + (size_t)grow * HID_F + c4);
        *(float4*)(&As[r][c4]) = v;
    }
#pragma unroll
    for (int i = 0; i < 5; i++) {
        int q  = tid + i * 256;
        int kr = q / 10;
        int c4 = (q % 10) * 4;
        *(float4*)(&Ws[kr][c4]) = *(const float4*)(W2 + (size_t)kr * OUT_F + c4);
    }
    __syncthreads();

    float acc[5] = {0.f, 0.f, 0.f, 0.f, 0.f};
#pragma unroll 8
    for (int k = 0; k < 128; k++) {
        float a = As[ty][k];
#pragma unroll
        for (int j = 0; j < 5; j++) acc[j] = fmaf(a, Ws[k][tx * 5 + j], acc[j]);
    }

    int grow = block_row + ty;
    if (grow < N_NODES) {
        float dv = d_dinv[grow];
#pragma unroll
        for (int j = 0; j < 5; j++)
            d_g2[(size_t)grow * OUT_F + tx * 5 + j] = acc[j] * dv;
    }
}

// ---------------- gather2 + log_softmax fused ----------------
__global__ __launch_bounds__(256) void gather2_kernel(const float* __restrict__ b2,
                                                      float* __restrict__ out) {
    int n    = (blockIdx.x * blockDim.x + threadIdx.x) >> 5;
    int lane = threadIdx.x & 31;
    if (n >= N_NODES) return;
    int start = d_rowptr[n];
    int end   = d_rowptr[n + 1];
    int deg   = end - start;

    const float4* G = (const float4*)d_g2;
    int sub  = lane / 10;       // 0..2 (lane 30,31 inactive)
    int comp = lane % 10;
    bool active = lane < 30;

    float4 a = make_float4(0.f, 0.f, 0.f, 0.f);
    for (int base = 0; base < deg; base += 3) {
        int idx = base + sub;
        if (active && idx < deg) {
            int s = d_csr_src[start + idx];
            float4 v = G[(size_t)s * 10 + comp];
            a.x += v.x; a.y += v.y; a.z += v.z; a.w += v.w;
        }
    }
#pragma unroll
    for (int off = 10; off <= 20; off += 10) {
        float vx = __shfl_sync(0xFFFFFFFFu, a.x, lane + off < 32 ? lane + off : lane);
        float vy = __shfl_sync(0xFFFFFFFFu, a.y, lane + off < 32 ? lane + off : lane);
        float vz = __shfl_sync(0xFFFFFFFFu, a.z, lane + off < 32 ? lane + off : lane);
        float vw = __shfl_sync(0xFFFFFFFFu, a.w, lane + off < 32 ? lane + off : lane);
        if (lane < 10 && lane + off < 30) { a.x += vx; a.y += vy; a.z += vz; a.w += vw; }
    }

    float dv = d_dinv[n];
    float4 vals = make_float4(-FLT_MAX, -FLT_MAX, -FLT_MAX, -FLT_MAX);
    if (lane < 10) {
        float4 self = G[(size_t)n * 10 + lane];
        float4 b = *(const float4*)(b2 + lane * 4);
        vals.x = dv * (a.x + self.x) + b.x;
        vals.y = dv * (a.y + self.y) + b.y;
        vals.z = dv * (a.z + self.z) + b.z;
        vals.w = dv * (a.w + self.w) + b.w;
    }
    float m = fmaxf(fmaxf(vals.x, vals.y), fmaxf(vals.z, vals.w));
#pragma unroll
    for (int o = 16; o > 0; o >>= 1) m = fmaxf(m, __shfl_xor_sync(0xFFFFFFFFu, m, o));
    float esum = 0.f;
    if (lane < 10) {
        esum = __expf(vals.x - m) + __expf(vals.y - m) +
               __expf(vals.z - m) + __expf(vals.w - m);
    }
#pragma unroll
    for (int o = 16; o > 0; o >>= 1) esum += __shfl_xor_sync(0xFFFFFFFFu, esum, o);

    float ls = m + __logf(esum);
    if (lane < 10) {
        float4 o4 = make_float4(vals.x - ls, vals.y - ls, vals.z - ls, vals.w - ls);
        *((float4*)(out + (size_t)n * OUT_F) + lane) = o4;
    }
}

// ---------------- launch ----------------
extern "C" void kernel_launch(void* const* d_in, const int* in_sizes, int n_in,
                              void* d_out, int out_size) {
    const float* x   = (const float*)d_in[0];
    const int*   ei  = (const int*)d_in[1];     // JAX demotes int64 -> int32
    const float* W1  = (const float*)d_in[2];
    const float* b1  = (const float*)d_in[3];
    const float* W2  = (const float*)d_in[4];
    const float* b2  = (const float*)d_in[5];
    float*       out = (float*)d_out;

    const int E = in_sizes[1] / 2;
    const int* src = ei;
    const int* dst = ei + E;

    // CSR build
    zero_deg_kernel<<<(N_NODES + 255) / 256, 256>>>();
    count_deg_kernel<<<2048, 256>>>(dst, E);
    dinv_kernel<<<(N_NODES + 255) / 256, 256>>>();
    blocksum_kernel<<<N_SCAN_BLOCKS, SCAN_B>>>();
    scan_tops_kernel<<<1, 128>>>();
    rowptr_kernel<<<N_SCAN_BLOCKS, SCAN_B>>>();
    fill_kernel<<<2048, 256>>>(src, dst, E);

    // layer 1
    gemm1_kernel<<<(N_NODES + 127) / 128, 256>>>(x, W1);
    gather1_kernel<<<(N_NODES * 32 + 255) / 256, 256>>>(b1);

    // layer 2
    gemm2_kernel<<<(N_NODES + 31) / 32, 256>>>(W2);
    gather2_kernel<<<(N_NODES * 32 + 255) / 256, 256>>>(b2, out);
}

// round 10
// speedup vs baseline: 3.0249x; 1.5719x over previous
#include <cuda_runtime.h>
#include <cuda_bf16.h>
#include <math.h>
#include <float.h>
#include <stdint.h>

#define N_NODES 100000
#define E_MAX   1600000
#define IN_F    512
#define HID_F   128
#define OUT_F   40

#define SCAN_B  1024
#define N_SCAN_BLOCKS ((N_NODES + SCAN_B - 1) / SCAN_B)   // 98

// ---------------- scratch (device globals; no allocation allowed) ----------------
__device__ int   d_deg    [N_NODES];
__device__ int   d_rowptr [N_NODES + 1];
__device__ int   d_cursor [N_NODES];
__device__ int   d_csr_src[E_MAX];
__device__ int   d_blocksum[N_SCAN_BLOCKS];
__device__ int   d_blockoff[N_SCAN_BLOCKS + 1];
__device__ float d_dinv[N_NODES];
__device__ float d_g1  [(size_t)N_NODES * HID_F];
__device__ float d_a1  [(size_t)N_NODES * HID_F];
__device__ float d_g2  [(size_t)N_NODES * OUT_F];
__device__ __nv_bfloat16 d_w1t_hi[(size_t)HID_F * IN_F];   // [n][k], k contiguous
__device__ __nv_bfloat16 d_w1t_lo[(size_t)HID_F * IN_F];

// ---------------- helpers ----------------
__device__ __forceinline__ uint32_t smem_u32(const void* p) {
    uint32_t a;
    asm("{ .reg .u64 t; cvta.to.shared.u64 t, %1; cvt.u32.u64 %0, t; }" : "=r"(a) : "l"(p));
    return a;
}
__device__ __forceinline__ void ldmatrix_x4(uint32_t* d, uint32_t addr) {
    asm volatile("ldmatrix.sync.aligned.m8n8.x4.shared.b16 {%0,%1,%2,%3}, [%4];"
                 : "=r"(d[0]), "=r"(d[1]), "=r"(d[2]), "=r"(d[3]) : "r"(addr));
}
__device__ __forceinline__ void mma_bf16(float* c, const uint32_t* a, uint32_t b0, uint32_t b1) {
    asm volatile("mma.sync.aligned.m16n8k16.row.col.f32.bf16.bf16.f32 "
                 "{%0,%1,%2,%3}, {%4,%5,%6,%7}, {%8,%9}, {%0,%1,%2,%3};"
                 : "+f"(c[0]), "+f"(c[1]), "+f"(c[2]), "+f"(c[3])
                 : "r"(a[0]), "r"(a[1]), "r"(a[2]), "r"(a[3]), "r"(b0), "r"(b1));
}

// ---------------- degree / norm ----------------
__global__ void zero_deg_kernel() {
    int i = blockIdx.x * blockDim.x + threadIdx.x;
    if (i < N_NODES) d_deg[i] = 0;
}

__global__ void count_deg_kernel(const int* __restrict__ dst, int E) {
    int i = blockIdx.x * blockDim.x + threadIdx.x;
    int stride = gridDim.x * blockDim.x;
    for (; i < E; i += stride) atomicAdd(&d_deg[dst[i]], 1);
}

__global__ void dinv_kernel() {
    int i = blockIdx.x * blockDim.x + threadIdx.x;
    if (i < N_NODES) d_dinv[i] = rsqrtf((float)d_deg[i] + 1.0f);
}

// ---------------- W1 transpose + bf16 split: [k][n] fp32 -> [n][k] bf16 hi/lo ----------------
__global__ void w1_split_kernel(const float* __restrict__ W1) {
    int i = blockIdx.x * blockDim.x + threadIdx.x;
    if (i < IN_F * HID_F) {
        int k = i / HID_F, n = i % HID_F;
        float v = W1[i];
        __nv_bfloat16 hi = __float2bfloat16(v);
        float lo_f = v - __bfloat162float(hi);
        d_w1t_hi[(size_t)n * IN_F + k] = hi;
        d_w1t_lo[(size_t)n * IN_F + k] = __float2bfloat16(lo_f);
    }
}

// ---------------- hierarchical scan ----------------
__global__ __launch_bounds__(SCAN_B) void blocksum_kernel() {
    __shared__ int sh[SCAN_B / 32];
    int i = blockIdx.x * SCAN_B + threadIdx.x;
    int v = (i < N_NODES) ? d_deg[i] : 0;
#pragma unroll
    for (int o = 16; o > 0; o >>= 1) v += __shfl_xor_sync(0xFFFFFFFFu, v, o);
    if ((threadIdx.x & 31) == 0) sh[threadIdx.x >> 5] = v;
    __syncthreads();
    if (threadIdx.x < SCAN_B / 32) {
        int s = sh[threadIdx.x];
#pragma unroll
        for (int o = 16; o > 0; o >>= 1) s += __shfl_xor_sync(0xFFFFFFFFu, s, o);
        if (threadIdx.x == 0) d_blocksum[blockIdx.x] = s;
    }
}

__global__ __launch_bounds__(128) void scan_tops_kernel() {
    __shared__ int sh[N_SCAN_BLOCKS];
    int tid = threadIdx.x;
    if (tid < N_SCAN_BLOCKS) sh[tid] = d_blocksum[tid];
    __syncthreads();
    if (tid == 0) {
        int run = 0;
        for (int i = 0; i < N_SCAN_BLOCKS; i++) { int t = sh[i]; sh[i] = run; run += t; }
        d_blockoff[N_SCAN_BLOCKS] = run;
    }
    __syncthreads();
    if (tid < N_SCAN_BLOCKS) d_blockoff[tid] = sh[tid];
}

__global__ __launch_bounds__(SCAN_B) void rowptr_kernel() {
    __shared__ int sh[SCAN_B];
    int tid = threadIdx.x;
    int i = blockIdx.x * SCAN_B + tid;
    int v = (i < N_NODES) ? d_deg[i] : 0;
    sh[tid] = v;
    __syncthreads();
    for (int off = 1; off < SCAN_B; off <<= 1) {
        int t = (tid >= off) ? sh[tid - off] : 0;
        __syncthreads();
        sh[tid] += t;
        __syncthreads();
    }
    if (i < N_NODES) {
        int excl = sh[tid] - v;
        d_rowptr[i] = d_blockoff[blockIdx.x] + excl;
        d_cursor[i] = 0;
    }
    if (i == N_NODES - 1) d_rowptr[N_NODES] = d_blockoff[N_SCAN_BLOCKS];
}

// ---------------- fill: bucket edges by dst ----------------
__global__ void fill_kernel(const int* __restrict__ src, const int* __restrict__ dst, int E) {
    int i = blockIdx.x * blockDim.x + threadIdx.x;
    int stride = gridDim.x * blockDim.x;
    for (; i < E; i += stride) {
        int d = dst[i];
        int pos = d_rowptr[d] + atomicAdd(&d_cursor[d], 1);
        d_csr_src[pos] = src[i];
    }
}

// ---------------- GEMM1 (mma.sync bf16, 3-pass split): g1 = (X @ W1) * dinv ----------------
// CTA tile 128x128, BK=32, 8 warps (4M x 2N), warp tile 32x64.
// SMEM rows padded to 40 halves (80B) -> conflict-free ldmatrix.
#define PK 40
__global__ __launch_bounds__(256, 2) void gemm1_mma_kernel(const float* __restrict__ X) {
    __shared__ __nv_bfloat16 sAh[128 * PK], sAl[128 * PK];
    __shared__ __nv_bfloat16 sBh[128 * PK], sBl[128 * PK];

    const int tid  = threadIdx.x;
    const int lane = tid & 31;
    const int w    = tid >> 5;
    const int wm   = w & 3;          // M quarter (32 rows)
    const int wn   = w >> 2;         // N half (64 cols)
    const int block_row = blockIdx.x * 128;

    const uint32_t uAh = smem_u32(sAh), uAl = smem_u32(sAl);
    const uint32_t uBh = smem_u32(sBh), uBl = smem_u32(sBl);

    float acc[2][8][4];
#pragma unroll
    for (int mt = 0; mt < 2; mt++)
#pragma unroll
        for (int nt = 0; nt < 8; nt++)
#pragma unroll
            for (int j = 0; j < 4; j++) acc[mt][nt][j] = 0.f;

    for (int kt = 0; kt < IN_F / 32; kt++) {        // 16 iterations
        __syncthreads();    // previous-iter compute done before overwrite
        // ---- A: 128 rows x 32 fp32 -> bf16 hi/lo into smem ----
#pragma unroll
        for (int i = 0; i < 4; i++) {
            int q  = tid + i * 256;          // float4 index 0..1023
            int r  = q >> 3;                 // row 0..127 (8 float4 per row)
            int c4 = (q & 7) * 4;            // col 0..28
            int grow = block_row + r;
            float4 v = make_float4(0.f, 0.f, 0.f, 0.f);
            if (grow < N_NODES)
                v = *(const float4*)(X + (size_t)grow * IN_F + kt * 32 + c4);
            __nv_bfloat162 h01, h23, l01, l23;
            h01.x = __float2bfloat16(v.x); h01.y = __float2bfloat16(v.y);
            h23.x = __float2bfloat16(v.z); h23.y = __float2bfloat16(v.w);
            l01.x = __float2bfloat16(v.x - __bfloat162float(h01.x));
            l01.y = __float2bfloat16(v.y - __bfloat162float(h01.y));
            l23.x = __float2bfloat16(v.z - __bfloat162float(h23.x));
            l23.y = __float2bfloat16(v.w - __bfloat162float(h23.y));
            *(__nv_bfloat162*)&sAh[r * PK + c4]     = h01;
            *(__nv_bfloat162*)&sAh[r * PK + c4 + 2] = h23;
            *(__nv_bfloat162*)&sAl[r * PK + c4]     = l01;
            *(__nv_bfloat162*)&sAl[r * PK + c4 + 2] = l23;
        }
        // ---- B: 128 n-rows x 32 halves (hi & lo) ----
#pragma unroll
        for (int i = 0; i < 2; i++) {
            int q  = tid + i * 256;          // 0..511
            int n  = q >> 2;                 // 0..127
            int kk = (q & 3) * 8;            // 0,8,16,24
            uint4 hv = *(const uint4*)(d_w1t_hi + (size_t)n * IN_F + kt * 32 + kk);
            uint4 lv = *(const uint4*)(d_w1t_lo + (size_t)n * IN_F + kt * 32 + kk);
            *(uint4*)&sBh[n * PK + kk] = hv;
            *(uint4*)&sBl[n * PK + kk] = lv;
        }
        __syncthreads();

        // ---- compute: 2 k16 steps ----
#pragma unroll
        for (int ks = 0; ks < 2; ks++) {
            uint32_t ah[2][4], al[2][4];
#pragma unroll
            for (int mt = 0; mt < 2; mt++) {
                int row  = wm * 32 + mt * 16 + (lane & 15);
                int koff = ks * 16 + (lane >> 4) * 8;
                uint32_t off = (uint32_t)(row * PK + koff) * 2;
                ldmatrix_x4(ah[mt], uAh + off);
                ldmatrix_x4(al[mt], uAl + off);
            }
#pragma unroll
            for (int g = 0; g < 4; g++) {    // each g covers 2 n8 tiles
                int n    = wn * 64 + g * 16 + ((lane >> 4) & 1) * 8 + (lane & 7);
                int koff = ks * 16 + ((lane >> 3) & 1) * 8;
                uint32_t off = (uint32_t)(n * PK + koff) * 2;
                uint32_t bh[4], bl[4];
                ldmatrix_x4(bh, uBh + off);
                ldmatrix_x4(bl, uBl + off);
#pragma unroll
                for (int t = 0; t < 2; t++) {
                    int nt = 2 * g + t;
#pragma unroll
                    for (int mt = 0; mt < 2; mt++) {
                        mma_bf16(acc[mt][nt], ah[mt], bh[2 * t], bh[2 * t + 1]);  // hh
                        mma_bf16(acc[mt][nt], ah[mt], bl[2 * t], bl[2 * t + 1]);  // hl
                        mma_bf16(acc[mt][nt], al[mt], bh[2 * t], bh[2 * t + 1]);  // lh
                    }
                }
            }
        }
    }

    // ---- epilogue: scale by dinv[row], store ----
#pragma unroll
    for (int mt = 0; mt < 2; mt++) {
        int r0 = block_row + wm * 32 + mt * 16 + (lane >> 2);
        int r1 = r0 + 8;
        float dv0 = (r0 < N_NODES) ? d_dinv[r0] : 0.f;
        float dv1 = (r1 < N_NODES) ? d_dinv[r1] : 0.f;
#pragma unroll
        for (int nt = 0; nt < 8; nt++) {
            int col = wn * 64 + nt * 8 + (lane & 3) * 2;
            if (r0 < N_NODES) {
                float2 o = make_float2(acc[mt][nt][0] * dv0, acc[mt][nt][1] * dv0);
                *(float2*)(d_g1 + (size_t)r0 * HID_F + col) = o;
            }
            if (r1 < N_NODES) {
                float2 o = make_float2(acc[mt][nt][2] * dv1, acc[mt][nt][3] * dv1);
                *(float2*)(d_g1 + (size_t)r1 * HID_F + col) = o;
            }
        }
    }
}

// ---------------- gather1: a1 = relu(dinv*(sum_in g1[src] + g1[n]) + b1) ----------------
__global__ __launch_bounds__(256) void gather1_kernel(const float* __restrict__ b1) {
    int n    = (blockIdx.x * blockDim.x + threadIdx.x) >> 5;
    int lane = threadIdx.x & 31;
    if (n >= N_NODES) return;
    int e   = d_rowptr[n];
    int end = d_rowptr[n + 1];

    const float4* G = (const float4*)d_g1;
    float4 a0 = make_float4(0.f, 0.f, 0.f, 0.f);
    float4 a1v = make_float4(0.f, 0.f, 0.f, 0.f);

    for (; e + 1 < end; e += 2) {
        int s0 = d_csr_src[e];
        int s1 = d_csr_src[e + 1];
        float4 v0 = G[(size_t)s0 * 32 + lane];
        float4 v1 = G[(size_t)s1 * 32 + lane];
        a0.x += v0.x; a0.y += v0.y; a0.z += v0.z; a0.w += v0.w;
        a1v.x += v1.x; a1v.y += v1.y; a1v.z += v1.z; a1v.w += v1.w;
    }
    if (e < end) {
        int s0 = d_csr_src[e];
        float4 v0 = G[(size_t)s0 * 32 + lane];
        a0.x += v0.x; a0.y += v0.y; a0.z += v0.z; a0.w += v0.w;
    }
    float4 self = G[(size_t)n * 32 + lane];
    float dv = d_dinv[n];
    float4 b = *(const float4*)(b1 + lane * 4);
    float4 o;
    o.x = fmaxf(dv * (a0.x + a1v.x + self.x) + b.x, 0.f);
    o.y = fmaxf(dv * (a0.y + a1v.y + self.y) + b.y, 0.f);
    o.z = fmaxf(dv * (a0.z + a1v.z + self.z) + b.z, 0.f);
    o.w = fmaxf(dv * (a0.w + a1v.w + self.w) + b.w, 0.f);
    *((float4*)d_a1 + (size_t)n * 32 + lane) = o;
}

// ---------------- GEMM2: g2 = (a1 @ W2) * dinv ----------------
__global__ __launch_bounds__(256) void gemm2_kernel(const float* __restrict__ W2) {
    __shared__ float As[32][132];
    __shared__ float Ws[128][40];
    const int tid = threadIdx.x;
    const int block_row = blockIdx.x * 32;
    const int tx = tid & 7;
    const int ty = tid >> 3;

#pragma unroll
    for (int i = 0; i < 4; i++) {
        int q  = tid + i * 256;
        int r  = q >> 5;
        int c4 = (q & 31) * 4;
        int grow = block_row + r;
        float4 v = make_float4(0.f, 0.f, 0.f, 0.f);
        if (grow < N_NODES)
            v = *(const float4*)(d_a1 + (size_t)grow * HID_F + c4);
        *(float4*)(&As[r][c4]) = v;
    }
#pragma unroll
    for (int i = 0; i < 5; i++) {
        int q  = tid + i * 256;
        int kr = q / 10;
        int c4 = (q % 10) * 4;
        *(float4*)(&Ws[kr][c4]) = *(const float4*)(W2 + (size_t)kr * OUT_F + c4);
    }
    __syncthreads();

    float acc[5] = {0.f, 0.f, 0.f, 0.f, 0.f};
#pragma unroll 8
    for (int k = 0; k < 128; k++) {
        float a = As[ty][k];
#pragma unroll
        for (int j = 0; j < 5; j++) acc[j] = fmaf(a, Ws[k][tx * 5 + j], acc[j]);
    }

    int grow = block_row + ty;
    if (grow < N_NODES) {
        float dv = d_dinv[grow];
#pragma unroll
        for (int j = 0; j < 5; j++)
            d_g2[(size_t)grow * OUT_F + tx * 5 + j] = acc[j] * dv;
    }
}

// ---------------- gather2 + log_softmax fused ----------------
__global__ __launch_bounds__(256) void gather2_kernel(const float* __restrict__ b2,
                                                      float* __restrict__ out) {
    int n    = (blockIdx.x * blockDim.x + threadIdx.x) >> 5;
    int lane = threadIdx.x & 31;
    if (n >= N_NODES) return;
    int start = d_rowptr[n];
    int end   = d_rowptr[n + 1];
    int deg   = end - start;

    const float4* G = (const float4*)d_g2;
    int sub  = lane / 10;
    int comp = lane % 10;
    bool active = lane < 30;

    float4 a = make_float4(0.f, 0.f, 0.f, 0.f);
    for (int base = 0; base < deg; base += 3) {
        int idx = base + sub;
        if (active && idx < deg) {
            int s = d_csr_src[start + idx];
            float4 v = G[(size_t)s * 10 + comp];
            a.x += v.x; a.y += v.y; a.z += v.z; a.w += v.w;
        }
    }
#pragma unroll
    for (int off = 10; off <= 20; off += 10) {
        float vx = __shfl_sync(0xFFFFFFFFu, a.x, lane + off < 32 ? lane + off : lane);
        float vy = __shfl_sync(0xFFFFFFFFu, a.y, lane + off < 32 ? lane + off : lane);
        float vz = __shfl_sync(0xFFFFFFFFu, a.z, lane + off < 32 ? lane + off : lane);
        float vw = __shfl_sync(0xFFFFFFFFu, a.w, lane + off < 32 ? lane + off : lane);
        if (lane < 10 && lane + off < 30) { a.x += vx; a.y += vy; a.z += vz; a.w += vw; }
    }

    float dv = d_dinv[n];
    float4 vals = make_float4(-FLT_MAX, -FLT_MAX, -FLT_MAX, -FLT_MAX);
    if (lane < 10) {
        float4 self = G[(size_t)n * 10 + lane];
        float4 b = *(const float4*)(b2 + lane * 4);
        vals.x = dv * (a.x + self.x) + b.x;
        vals.y = dv * (a.y + self.y) + b.y;
        vals.z = dv * (a.z + self.z) + b.z;
        vals.w = dv * (a.w + self.w) + b.w;
    }
    float m = fmaxf(fmaxf(vals.x, vals.y), fmaxf(vals.z, vals.w));
#pragma unroll
    for (int o = 16; o > 0; o >>= 1) m = fmaxf(m, __shfl_xor_sync(0xFFFFFFFFu, m, o));
    float esum = 0.f;
    if (lane < 10) {
        esum = __expf(vals.x - m) + __expf(vals.y - m) +
               __expf(vals.z - m) + __expf(vals.w - m);
    }
#pragma unroll
    for (int o = 16; o > 0; o >>= 1) esum += __shfl_xor_sync(0xFFFFFFFFu, esum, o);

    float ls = m + __logf(esum);
    if (lane < 10) {
        float4 o4 = make_float4(vals.x - ls, vals.y - ls, vals.z - ls, vals.w - ls);
        *((float4*)(out + (size_t)n * OUT_F) + lane) = o4;
    }
}

// ---------------- launch ----------------
extern "C" void kernel_launch(void* const* d_in, const int* in_sizes, int n_in,
                              void* d_out, int out_size) {
    const float* x   = (const float*)d_in[0];
    const int*   ei  = (const int*)d_in[1];
    const float* W1  = (const float*)d_in[2];
    const float* b1  = (const float*)d_in[3];
    const float* W2  = (const float*)d_in[4];
    const float* b2  = (const float*)d_in[5];
    float*       out = (float*)d_out;

    const int E = in_sizes[1] / 2;
    const int* src = ei;
    const int* dst = ei + E;

    // CSR build + weight prep
    zero_deg_kernel<<<(N_NODES + 255) / 256, 256>>>();
    count_deg_kernel<<<2048, 256>>>(dst, E);
    w1_split_kernel<<<(IN_F * HID_F + 255) / 256, 256>>>(W1);
    dinv_kernel<<<(N_NODES + 255) / 256, 256>>>();
    blocksum_kernel<<<N_SCAN_BLOCKS, SCAN_B>>>();
    scan_tops_kernel<<<1, 128>>>();
    rowptr_kernel<<<N_SCAN_BLOCKS, SCAN_B>>>();
    fill_kernel<<<2048, 256>>>(src, dst, E);

    // layer 1
    gemm1_mma_kernel<<<(N_NODES + 127) / 128, 256>>>(x);
    gather1_kernel<<<(N_NODES * 32 + 255) / 256, 256>>>(b1);

    // layer 2
    gemm2_kernel<<<(N_NODES + 31) / 32, 256>>>(W2);
    gather2_kernel<<<(N_NODES * 32 + 255) / 256, 256>>>(b2, out);
}

// round 11
// speedup vs baseline: 3.5069x; 1.1594x over previous
#include <cuda_runtime.h>
#include <cuda_bf16.h>
#include <math.h>
#include <float.h>
#include <stdint.h>

#define N_NODES 100000
#define E_MAX   1600000
#define IN_F    512
#define HID_F   128
#define OUT_F   40
#define N2_PAD  64

#define SCAN_B  1024
#define N_SCAN_BLOCKS ((N_NODES + SCAN_B - 1) / SCAN_B)   // 98

// ---------------- scratch (device globals; no allocation allowed) ----------------
__device__ int   d_deg    [N_NODES];
__device__ int   d_rowptr [N_NODES + 1];
__device__ int   d_cursor [N_NODES];
__device__ int   d_csr_src[E_MAX];
__device__ int   d_blocksum[N_SCAN_BLOCKS];
__device__ int   d_blockoff[N_SCAN_BLOCKS + 1];
__device__ float d_dinv[N_NODES];
__device__ float d_g1  [(size_t)N_NODES * HID_F];
__device__ float d_a1  [(size_t)N_NODES * HID_F];
__device__ float d_g2  [(size_t)N_NODES * OUT_F];
__device__ __nv_bfloat16 d_w1t_hi[(size_t)HID_F * IN_F];   // [n][k]
__device__ __nv_bfloat16 d_w1t_lo[(size_t)HID_F * IN_F];
__device__ __nv_bfloat16 d_w2t_hi[(size_t)N2_PAD * HID_F]; // [n][k], zero-padded n>=40
__device__ __nv_bfloat16 d_w2t_lo[(size_t)N2_PAD * HID_F];

// ---------------- helpers ----------------
__device__ __forceinline__ uint32_t smem_u32(const void* p) {
    uint32_t a;
    asm("{ .reg .u64 t; cvta.to.shared.u64 t, %1; cvt.u32.u64 %0, t; }" : "=r"(a) : "l"(p));
    return a;
}
__device__ __forceinline__ void ldmatrix_x4(uint32_t* d, uint32_t addr) {
    asm volatile("ldmatrix.sync.aligned.m8n8.x4.shared.b16 {%0,%1,%2,%3}, [%4];"
                 : "=r"(d[0]), "=r"(d[1]), "=r"(d[2]), "=r"(d[3]) : "r"(addr));
}
__device__ __forceinline__ void mma_bf16(float* c, const uint32_t* a, uint32_t b0, uint32_t b1) {
    asm volatile("mma.sync.aligned.m16n8k16.row.col.f32.bf16.bf16.f32 "
                 "{%0,%1,%2,%3}, {%4,%5,%6,%7}, {%8,%9}, {%0,%1,%2,%3};"
                 : "+f"(c[0]), "+f"(c[1]), "+f"(c[2]), "+f"(c[3])
                 : "r"(a[0]), "r"(a[1]), "r"(a[2]), "r"(a[3]), "r"(b0), "r"(b1));
}

// ---------------- zero degree ----------------
__global__ void zero_deg_kernel() {
    int i = blockIdx.x * blockDim.x + threadIdx.x;
    if (i < N_NODES) d_deg[i] = 0;
}

// ---------------- fat kernel: count_deg + w1 split + w2 split ----------------
// blocks [0,1536): count_deg; [1536,1792): w1 split; [1792,1824): w2 split
#define CNT_BLOCKS 1536
__global__ void prep_kernel(const int* __restrict__ dst, int E, 
                            const float* __restrict__ W1, const float* __restrict__ W2) {
    int b = blockIdx.x;
    if (b < CNT_BLOCKS) {
        int i = b * blockDim.x + threadIdx.x;
        int stride = CNT_BLOCKS * blockDim.x;
        for (; i < E; i += stride) atomicAdd(&d_deg[dst[i]], 1);
    } else if (b < CNT_BLOCKS + 256) {
        int i = (b - CNT_BLOCKS) * blockDim.x + threadIdx.x;   // 0..65535
        int k = i / HID_F, n = i % HID_F;
        float v = W1[i];
        __nv_bfloat16 hi = __float2bfloat16(v);
        d_w1t_hi[(size_t)n * IN_F + k] = hi;
        d_w1t_lo[(size_t)n * IN_F + k] = __float2bfloat16(v - __bfloat162float(hi));
    } else {
        int i = (b - CNT_BLOCKS - 256) * blockDim.x + threadIdx.x;  // 0..8191
        int k = i / N2_PAD, n = i % N2_PAD;
        float v = (n < OUT_F) ? W2[k * OUT_F + n] : 0.f;
        __nv_bfloat16 hi = __float2bfloat16(v);
        d_w2t_hi[(size_t)n * HID_F + k] = hi;
        d_w2t_lo[(size_t)n * HID_F + k] = __float2bfloat16(v - __bfloat162float(hi));
    }
}

// ---------------- fat kernel: dinv + blocksum (98 blocks x 1024) ----------------
__global__ __launch_bounds__(SCAN_B) void dinv_blocksum_kernel() {
    __shared__ int sh[SCAN_B / 32];
    int i = blockIdx.x * SCAN_B + threadIdx.x;
    int v = 0;
    if (i < N_NODES) {
        v = d_deg[i];
        d_dinv[i] = rsqrtf((float)v + 1.0f);
    }
    int s = v;
#pragma unroll
    for (int o = 16; o > 0; o >>= 1) s += __shfl_xor_sync(0xFFFFFFFFu, s, o);
    if ((threadIdx.x & 31) == 0) sh[threadIdx.x >> 5] = s;
    __syncthreads();
    if (threadIdx.x < SCAN_B / 32) {
        int t = sh[threadIdx.x];
#pragma unroll
        for (int o = 16; o > 0; o >>= 1) t += __shfl_xor_sync(0xFFFFFFFFu, t, o);
        if (threadIdx.x == 0) d_blocksum[blockIdx.x] = t;
    }
}

__global__ __launch_bounds__(128) void scan_tops_kernel() {
    __shared__ int sh[N_SCAN_BLOCKS];
    int tid = threadIdx.x;
    if (tid < N_SCAN_BLOCKS) sh[tid] = d_blocksum[tid];
    __syncthreads();
    if (tid == 0) {
        int run = 0;
        for (int i = 0; i < N_SCAN_BLOCKS; i++) { int t = sh[i]; sh[i] = run; run += t; }
        d_blockoff[N_SCAN_BLOCKS] = run;
    }
    __syncthreads();
    if (tid < N_SCAN_BLOCKS) d_blockoff[tid] = sh[tid];
}

__global__ __launch_bounds__(SCAN_B) void rowptr_kernel() {
    __shared__ int sh[SCAN_B];
    int tid = threadIdx.x;
    int i = blockIdx.x * SCAN_B + tid;
    int v = (i < N_NODES) ? d_deg[i] : 0;
    sh[tid] = v;
    __syncthreads();
    for (int off = 1; off < SCAN_B; off <<= 1) {
        int t = (tid >= off) ? sh[tid - off] : 0;
        __syncthreads();
        sh[tid] += t;
        __syncthreads();
    }
    if (i < N_NODES) {
        int excl = sh[tid] - v;
        d_rowptr[i] = d_blockoff[blockIdx.x] + excl;
        d_cursor[i] = 0;
    }
    if (i == N_NODES - 1) d_rowptr[N_NODES] = d_blockoff[N_SCAN_BLOCKS];
}

// ---------------- GEMM1 (mma.sync bf16, 3-pass) + fill fat kernel ----------------
// blocks [0, GEMM1_BLOCKS): 128x128 GEMM tile; [GEMM1_BLOCKS, +FILL_BLOCKS): CSR fill
#define PK 40
#define GEMM1_BLOCKS ((N_NODES + 127) / 128)       // 782
#define FILL_BLOCKS  512
__global__ __launch_bounds__(256, 2) void gemm1_fill_kernel(const float* __restrict__ X,
                                                            const int* __restrict__ src,
                                                            const int* __restrict__ dst, int E) {
    if (blockIdx.x >= GEMM1_BLOCKS) {
        // ---------------- fill part ----------------
        int i = (blockIdx.x - GEMM1_BLOCKS) * blockDim.x + threadIdx.x;
        int stride = FILL_BLOCKS * blockDim.x;
        for (; i < E; i += stride) {
            int d = dst[i];
            int pos = d_rowptr[d] + atomicAdd(&d_cursor[d], 1);
            d_csr_src[pos] = src[i];
        }
        return;
    }
    __shared__ __nv_bfloat16 sAh[128 * PK], sAl[128 * PK];
    __shared__ __nv_bfloat16 sBh[128 * PK], sBl[128 * PK];

    const int tid  = threadIdx.x;
    const int lane = tid & 31;
    const int w    = tid >> 5;
    const int wm   = w & 3;
    const int wn   = w >> 2;
    const int block_row = blockIdx.x * 128;

    const uint32_t uAh = smem_u32(sAh), uAl = smem_u32(sAl);
    const uint32_t uBh = smem_u32(sBh), uBl = smem_u32(sBl);

    float acc[2][8][4];
#pragma unroll
    for (int mt = 0; mt < 2; mt++)
#pragma unroll
        for (int nt = 0; nt < 8; nt++)
#pragma unroll
            for (int j = 0; j < 4; j++) acc[mt][nt][j] = 0.f;

    for (int kt = 0; kt < IN_F / 32; kt++) {
        __syncthreads();
#pragma unroll
        for (int i = 0; i < 4; i++) {
            int q  = tid + i * 256;
            int r  = q >> 3;
            int c4 = (q & 7) * 4;
            int grow = block_row + r;
            float4 v = make_float4(0.f, 0.f, 0.f, 0.f);
            if (grow < N_NODES)
                v = *(const float4*)(X + (size_t)grow * IN_F + kt * 32 + c4);
            __nv_bfloat162 h01, h23, l01, l23;
            h01.x = __float2bfloat16(v.x); h01.y = __float2bfloat16(v.y);
            h23.x = __float2bfloat16(v.z); h23.y = __float2bfloat16(v.w);
            l01.x = __float2bfloat16(v.x - __bfloat162float(h01.x));
            l01.y = __float2bfloat16(v.y - __bfloat162float(h01.y));
            l23.x = __float2bfloat16(v.z - __bfloat162float(h23.x));
            l23.y = __float2bfloat16(v.w - __bfloat162float(h23.y));
            *(__nv_bfloat162*)&sAh[r * PK + c4]     = h01;
            *(__nv_bfloat162*)&sAh[r * PK + c4 + 2] = h23;
            *(__nv_bfloat162*)&sAl[r * PK + c4]     = l01;
            *(__nv_bfloat162*)&sAl[r * PK + c4 + 2] = l23;
        }
#pragma unroll
        for (int i = 0; i < 2; i++) {
            int q  = tid + i * 256;
            int n  = q >> 2;
            int kk = (q & 3) * 8;
            uint4 hv = *(const uint4*)(d_w1t_hi + (size_t)n * IN_F + kt * 32 + kk);
            uint4 lv = *(const uint4*)(d_w1t_lo + (size_t)n * IN_F + kt * 32 + kk);
            *(uint4*)&sBh[n * PK + kk] = hv;
            *(uint4*)&sBl[n * PK + kk] = lv;
        }
        __syncthreads();

#pragma unroll
        for (int ks = 0; ks < 2; ks++) {
            uint32_t ah[2][4], al[2][4];
#pragma unroll
            for (int mt = 0; mt < 2; mt++) {
                int row  = wm * 32 + mt * 16 + (lane & 15);
                int koff = ks * 16 + (lane >> 4) * 8;
                uint32_t off = (uint32_t)(row * PK + koff) * 2;
                ldmatrix_x4(ah[mt], uAh + off);
                ldmatrix_x4(al[mt], uAl + off);
            }
#pragma unroll
            for (int g = 0; g < 4; g++) {
                int n    = wn * 64 + g * 16 + ((lane >> 4) & 1) * 8 + (lane & 7);
                int koff = ks * 16 + ((lane >> 3) & 1) * 8;
                uint32_t off = (uint32_t)(n * PK + koff) * 2;
                uint32_t bh[4], bl[4];
                ldmatrix_x4(bh, uBh + off);
                ldmatrix_x4(bl, uBl + off);
#pragma unroll
                for (int t = 0; t < 2; t++) {
                    int nt = 2 * g + t;
#pragma unroll
                    for (int mt = 0; mt < 2; mt++) {
                        mma_bf16(acc[mt][nt], ah[mt], bh[2 * t], bh[2 * t + 1]);
                        mma_bf16(acc[mt][nt], ah[mt], bl[2 * t], bl[2 * t + 1]);
                        mma_bf16(acc[mt][nt], al[mt], bh[2 * t], bh[2 * t + 1]);
                    }
                }
            }
        }
    }

#pragma unroll
    for (int mt = 0; mt < 2; mt++) {
        int r0 = block_row + wm * 32 + mt * 16 + (lane >> 2);
        int r1 = r0 + 8;
        float dv0 = (r0 < N_NODES) ? d_dinv[r0] : 0.f;
        float dv1 = (r1 < N_NODES) ? d_dinv[r1] : 0.f;
#pragma unroll
        for (int nt = 0; nt < 8; nt++) {
            int col = wn * 64 + nt * 8 + (lane & 3) * 2;
            if (r0 < N_NODES) {
                float2 o = make_float2(acc[mt][nt][0] * dv0, acc[mt][nt][1] * dv0);
                *(float2*)(d_g1 + (size_t)r0 * HID_F + col) = o;
            }
            if (r1 < N_NODES) {
                float2 o = make_float2(acc[mt][nt][2] * dv1, acc[mt][nt][3] * dv1);
                *(float2*)(d_g1 + (size_t)r1 * HID_F + col) = o;
            }
        }
    }
}

// ---------------- gather1: a1 = relu(dinv*(sum_in g1[src] + g1[n]) + b1), 4-way unroll ----------------
__global__ __launch_bounds__(256) void gather1_kernel(const float* __restrict__ b1) {
    int n    = (blockIdx.x * blockDim.x + threadIdx.x) >> 5;
    int lane = threadIdx.x & 31;
    if (n >= N_NODES) return;
    int e   = d_rowptr[n];
    int end = d_rowptr[n + 1];

    const float4* G = (const float4*)d_g1;
    float4 a0 = make_float4(0.f, 0.f, 0.f, 0.f);
    float4 a1v = make_float4(0.f, 0.f, 0.f, 0.f);
    float4 a2 = make_float4(0.f, 0.f, 0.f, 0.f);
    float4 a3 = make_float4(0.f, 0.f, 0.f, 0.f);

    for (; e + 3 < end; e += 4) {
        int s0 = d_csr_src[e];
        int s1 = d_csr_src[e + 1];
        int s2 = d_csr_src[e + 2];
        int s3 = d_csr_src[e + 3];
        float4 v0 = G[(size_t)s0 * 32 + lane];
        float4 v1 = G[(size_t)s1 * 32 + lane];
        float4 v2 = G[(size_t)s2 * 32 + lane];
        float4 v3 = G[(size_t)s3 * 32 + lane];
        a0.x += v0.x; a0.y += v0.y; a0.z += v0.z; a0.w += v0.w;
        a1v.x += v1.x; a1v.y += v1.y; a1v.z += v1.z; a1v.w += v1.w;
        a2.x += v2.x; a2.y += v2.y; a2.z += v2.z; a2.w += v2.w;
        a3.x += v3.x; a3.y += v3.y; a3.z += v3.z; a3.w += v3.w;
    }
    for (; e < end; e++) {
        int s0 = d_csr_src[e];
        float4 v0 = G[(size_t)s0 * 32 + lane];
        a0.x += v0.x; a0.y += v0.y; a0.z += v0.z; a0.w += v0.w;
    }
    float4 self = G[(size_t)n * 32 + lane];
    float dv = d_dinv[n];
    float4 b = *(const float4*)(b1 + lane * 4);
    float4 o;
    o.x = fmaxf(dv * (a0.x + a1v.x + a2.x + a3.x + self.x) + b.x, 0.f);
    o.y = fmaxf(dv * (a0.y + a1v.y + a2.y + a3.y + self.y) + b.y, 0.f);
    o.z = fmaxf(dv * (a0.z + a1v.z + a2.z + a3.z + self.z) + b.z, 0.f);
    o.w = fmaxf(dv * (a0.w + a1v.w + a2.w + a3.w + self.w) + b.w, 0.f);
    *((float4*)d_a1 + (size_t)n * 32 + lane) = o;
}

// ---------------- GEMM2 (mma.sync bf16, 3-pass): g2 = (a1 @ W2) * dinv ----------------
// CTA tile 128x64(40 real), K=128 in 4 chunks of 32. 8 warps = 4M x 2N, warp 32x32.
__global__ __launch_bounds__(256, 2) void gemm2_mma_kernel() {
    __shared__ __nv_bfloat16 sAh[128 * PK], sAl[128 * PK];
    __shared__ __nv_bfloat16 sBh[N2_PAD * PK], sBl[N2_PAD * PK];

    const int tid  = threadIdx.x;
    const int lane = tid & 31;
    const int w    = tid >> 5;
    const int wm   = w & 3;
    const int wn   = w >> 2;
    const int block_row = blockIdx.x * 128;

    const uint32_t uAh = smem_u32(sAh), uAl = smem_u32(sAl);
    const uint32_t uBh = smem_u32(sBh), uBl = smem_u32(sBl);

    float acc[2][4][4];
#pragma unroll
    for (int mt = 0; mt < 2; mt++)
#pragma unroll
        for (int nt = 0; nt < 4; nt++)
#pragma unroll
            for (int j = 0; j < 4; j++) acc[mt][nt][j] = 0.f;

    for (int kt = 0; kt < HID_F / 32; kt++) {     // 4 iterations
        __syncthreads();
        // A: 128 rows x 32 fp32 from d_a1, split hi/lo
#pragma unroll
        for (int i = 0; i < 4; i++) {
            int q  = tid + i * 256;
            int r  = q >> 3;
            int c4 = (q & 7) * 4;
            int grow = block_row + r;
            float4 v = make_float4(0.f, 0.f, 0.f, 0.f);
            if (grow < N_NODES)
                v = *(const float4*)(d_a1 + (size_t)grow * HID_F + kt * 32 + c4);
            __nv_bfloat162 h01, h23, l01, l23;
            h01.x = __float2bfloat16(v.x); h01.y = __float2bfloat16(v.y);
            h23.x = __float2bfloat16(v.z); h23.y = __float2bfloat16(v.w);
            l01.x = __float2bfloat16(v.x - __bfloat162float(h01.x));
            l01.y = __float2bfloat16(v.y - __bfloat162float(h01.y));
            l23.x = __float2bfloat16(v.z - __bfloat162float(h23.x));
            l23.y = __float2bfloat16(v.w - __bfloat162float(h23.y));
            *(__nv_bfloat162*)&sAh[r * PK + c4]     = h01;
            *(__nv_bfloat162*)&sAh[r * PK + c4 + 2] = h23;
            *(__nv_bfloat162*)&sAl[r * PK + c4]     = l01;
            *(__nv_bfloat162*)&sAl[r * PK + c4 + 2] = l23;
        }
        // B: 64 n-rows x 32 halves (pre-split, padded)
        {
            int q  = tid;                    // 0..255 = 64 rows x 4 uint4
            int n  = q >> 2;
            int kk = (q & 3) * 8;
            uint4 hv = *(const uint4*)(d_w2t_hi + (size_t)n * HID_F + kt * 32 + kk);
            uint4 lv = *(const uint4*)(d_w2t_lo + (size_t)n * HID_F + kt * 32 + kk);
            *(uint4*)&sBh[n * PK + kk] = hv;
            *(uint4*)&sBl[n * PK + kk] = lv;
        }
        __syncthreads();

#pragma unroll
        for (int ks = 0; ks < 2; ks++) {
            uint32_t ah[2][4], al[2][4];
#pragma unroll
            for (int mt = 0; mt < 2; mt++) {
                int row  = wm * 32 + mt * 16 + (lane & 15);
                int koff = ks * 16 + (lane >> 4) * 8;
                uint32_t off = (uint32_t)(row * PK + koff) * 2;
                ldmatrix_x4(ah[mt], uAh + off);
                ldmatrix_x4(al[mt], uAl + off);
            }
#pragma unroll
            for (int g = 0; g < 2; g++) {
                int n    = wn * 32 + g * 16 + ((lane >> 4) & 1) * 8 + (lane & 7);
                int koff = ks * 16 + ((lane >> 3) & 1) * 8;
                uint32_t off = (uint32_t)(n * PK + koff) * 2;
                uint32_t bh[4], bl[4];
                ldmatrix_x4(bh, uBh + off);
                ldmatrix_x4(bl, uBl + off);
#pragma unroll
                for (int t = 0; t < 2; t++) {
                    int nt = 2 * g + t;
#pragma unroll
                    for (int mt = 0; mt < 2; mt++) {
                        mma_bf16(acc[mt][nt], ah[mt], bh[2 * t], bh[2 * t + 1]);
                        mma_bf16(acc[mt][nt], ah[mt], bl[2 * t], bl[2 * t + 1]);
                        mma_bf16(acc[mt][nt], al[mt], bh[2 * t], bh[2 * t + 1]);
                    }
                }
            }
        }
    }

#pragma unroll
    for (int mt = 0; mt < 2; mt++) {
        int r0 = block_row + wm * 32 + mt * 16 + (lane >> 2);
        int r1 = r0 + 8;
        float dv0 = (r0 < N_NODES) ? d_dinv[r0] : 0.f;
        float dv1 = (r1 < N_NODES) ? d_dinv[r1] : 0.f;
#pragma unroll
        for (int nt = 0; nt < 4; nt++) {
            int col = wn * 32 + nt * 8 + (lane & 3) * 2;
            if (col < OUT_F) {
                if (r0 < N_NODES) {
                    float2 o = make_float2(acc[mt][nt][0] * dv0, acc[mt][nt][1] * dv0);
                    *(float2*)(d_g2 + (size_t)r0 * OUT_F + col) = o;
                }
                if (r1 < N_NODES) {
                    float2 o = make_float2(acc[mt][nt][2] * dv1, acc[mt][nt][3] * dv1);
                    *(float2*)(d_g2 + (size_t)r1 * OUT_F + col) = o;
                }
            }
        }
    }
}

// ---------------- gather2 + log_softmax fused ----------------
__global__ __launch_bounds__(256) void gather2_kernel(const float* __restrict__ b2,
                                                      float* __restrict__ out) {
    int n    = (blockIdx.x * blockDim.x + threadIdx.x) >> 5;
    int lane = threadIdx.x & 31;
    if (n >= N_NODES) return;
    int start = d_rowptr[n];
    int end   = d_rowptr[n + 1];
    int deg   = end - start;

    const float4* G = (const float4*)d_g2;
    int sub  = lane / 10;
    int comp = lane % 10;
    bool active = lane < 30;

    float4 a = make_float4(0.f, 0.f, 0.f, 0.f);
    for (int base = 0; base < deg; base += 3) {
        int idx = base + sub;
        if (active && idx < deg) {
            int s = d_csr_src[start + idx];
            float4 v = G[(size_t)s * 10 + comp];
            a.x += v.x; a.y += v.y; a.z += v.z; a.w += v.w;
        }
    }
#pragma unroll
    for (int off = 10; off <= 20; off += 10) {
        float vx = __shfl_sync(0xFFFFFFFFu, a.x, lane + off < 32 ? lane + off : lane);
        float vy = __shfl_sync(0xFFFFFFFFu, a.y, lane + off < 32 ? lane + off : lane);
        float vz = __shfl_sync(0xFFFFFFFFu, a.z, lane + off < 32 ? lane + off : lane);
        float vw = __shfl_sync(0xFFFFFFFFu, a.w, lane + off < 32 ? lane + off : lane);
        if (lane < 10 && lane + off < 30) { a.x += vx; a.y += vy; a.z += vz; a.w += vw; }
    }

    float dv = d_dinv[n];
    float4 vals = make_float4(-FLT_MAX, -FLT_MAX, -FLT_MAX, -FLT_MAX);
    if (lane < 10) {
        float4 self = G[(size_t)n * 10 + lane];
        float4 b = *(const float4*)(b2 + lane * 4);
        vals.x = dv * (a.x + self.x) + b.x;
        vals.y = dv * (a.y + self.y) + b.y;
        vals.z = dv * (a.z + self.z) + b.z;
        vals.w = dv * (a.w + self.w) + b.w;
    }
    float m = fmaxf(fmaxf(vals.x, vals.y), fmaxf(vals.z, vals.w));
#pragma unroll
    for (int o = 16; o > 0; o >>= 1) m = fmaxf(m, __shfl_xor_sync(0xFFFFFFFFu, m, o));
    float esum = 0.f;
    if (lane < 10) {
        esum = __expf(vals.x - m) + __expf(vals.y - m) +
               __expf(vals.z - m) + __expf(vals.w - m);
    }
#pragma unroll
    for (int o = 16; o > 0; o >>= 1) esum += __shfl_xor_sync(0xFFFFFFFFu, esum, o);

    float ls = m + __logf(esum);
    if (lane < 10) {
        float4 o4 = make_float4(vals.x - ls, vals.y - ls, vals.z - ls, vals.w - ls);
        *((float4*)(out + (size_t)n * OUT_F) + lane) = o4;
    }
}

// ---------------- launch ----------------
extern "C" void kernel_launch(void* const* d_in, const int* in_sizes, int n_in,
                              void* d_out, int out_size) {
    const float* x   = (const float*)d_in[0];
    const int*   ei  = (const int*)d_in[1];
    const float* W1  = (const float*)d_in[2];
    const float* b1  = (const float*)d_in[3];
    const float* W2  = (const float*)d_in[4];
    const float* b2  = (const float*)d_in[5];
    float*       out = (float*)d_out;

    const int E = in_sizes[1] / 2;
    const int* src = ei;
    const int* dst = ei + E;

    zero_deg_kernel<<<(N_NODES + 255) / 256, 256>>>();
    prep_kernel<<<CNT_BLOCKS + 256 + 32, 256>>>(dst, E, W1, W2);
    dinv_blocksum_kernel<<<N_SCAN_BLOCKS, SCAN_B>>>();
    scan_tops_kernel<<<1, 128>>>();
    rowptr_kernel<<<N_SCAN_BLOCKS, SCAN_B>>>();

    gemm1_fill_kernel<<<GEMM1_BLOCKS + FILL_BLOCKS, 256>>>(x, src, dst, E);
    gather1_kernel<<<(N_NODES * 32 + 255) / 256, 256>>>(b1);

    gemm2_mma_kernel<<<(N_NODES + 127) / 128, 256>>>();
    gather2_kernel<<<(N_NODES * 32 + 255) / 256, 256>>>(b2, out);
}